// round 11
// baseline (speedup 1.0000x reference)
#include <cuda_runtime.h>
#include <math.h>
#include <stdint.h>

#define BATCH 8
#define CH    384
#define OUTC  256
#define KD    32
#define RAD   3
#define DIAM  7
#define NTAP  49

// ---------------- scratch ----------------
__device__ float g_g1  [BATCH*3*96*96];
__device__ float g_g2  [BATCH*3*192*192];
__device__ float g_p1  [BATCH*KD*96*96];
__device__ float g_p2  [BATCH*KD*192*192];
__device__ float g_c1  [BATCH*NTAP*96*96];
__device__ float g_c2  [BATCH*NTAP*192*192];
__device__ float g_s2  [(size_t)BATCH*CH*96*96];
__device__ float g_s4  [(size_t)BATCH*CH*192*192];
__device__ float g_weff[OUTC*CH];
__device__ float g_beff[OUTC];

__device__ __forceinline__ int refl(int i, int n) {
    if (i < 0) i = -i;
    if (i >= n) i = 2*n - 2 - i;
    return i;
}
__device__ __forceinline__ uint32_t f2tf32(float x) {
    uint32_t u;
    asm("cvt.rna.tf32.f32 %0, %1;" : "=r"(u) : "f"(x));
    return u;
}

// ---------------- W_eff = P + 0.1 P F ; b_eff = pb + 0.1 P fb (tf32-rounded W) ----------------
__global__ void weff_kernel(const float* __restrict__ Pw, const float* __restrict__ pb,
                            const float* __restrict__ Fw, const float* __restrict__ fb,
                            float* __restrict__ Weff, float* __restrict__ beff) {
    int idx = blockIdx.x * blockDim.x + threadIdx.x;
    if (idx < OUTC*CH) {
        int o = idx / CH, c = idx % CH;
        float acc = 0.f;
        #pragma unroll 4
        for (int k = 0; k < CH; k++) acc += Pw[o*CH + k] * Fw[k*CH + c];
        Weff[idx] = __uint_as_float(f2tf32(Pw[o*CH + c] + 0.1f * acc));
    }
    if (idx < OUTC) {
        float a = 0.f;
        for (int k = 0; k < CH; k++) a += Pw[idx*CH + k] * fb[k];
        beff[idx] = pb[idx] + 0.1f * a;
    }
}

// ---------------- adaptive avg pool ----------------
__global__ void pool_kernel(const float* __restrict__ g, float* __restrict__ out,
                            int OH, int OW, int F) {
    int idx = blockIdx.x * blockDim.x + threadIdx.x;
    int total = BATCH * 3 * OH * OW;
    if (idx >= total) return;
    int ox = idx % OW; int t = idx / OW;
    int oy = t % OH;   t /= OH;
    int c  = t % 3;    int b = t / 3;
    const float* p = g + (((size_t)(b*3 + c)*768) + (size_t)oy*F)*768 + (size_t)ox*F;
    float s = 0.f;
    for (int i = 0; i < F; i++)
        for (int j = 0; j < F; j++)
            s += p[i*768 + j];
    out[idx] = s / (float)(F*F);
}

// ---------------- range projection MLP: 3 -> 32 (gelu) -> 32, CHANNEL-major out ----------------
__global__ void rproj_kernel(const float* __restrict__ g,
                             const float* __restrict__ w1, const float* __restrict__ b1,
                             const float* __restrict__ w2, const float* __restrict__ b2,
                             float* __restrict__ proj, int GH, int GW) {
    __shared__ float sw1[KD*3], sb1[KD], sw2[KD*KD], sb2[KD];
    int tid = threadIdx.x;
    for (int i = tid; i < KD*3;  i += blockDim.x) sw1[i] = w1[i];
    for (int i = tid; i < KD;    i += blockDim.x) { sb1[i] = b1[i]; sb2[i] = b2[i]; }
    for (int i = tid; i < KD*KD; i += blockDim.x) sw2[i] = w2[i];
    __syncthreads();
    int idx = blockIdx.x * blockDim.x + tid;
    int plane = GH * GW;
    if (idx >= BATCH * plane) return;
    int b = idx / plane, pix = idx % plane;
    float g0 = g[(size_t)(b*3 + 0)*plane + pix];
    float g1v = g[(size_t)(b*3 + 1)*plane + pix];
    float g2v = g[(size_t)(b*3 + 2)*plane + pix];
    float h[KD];
    #pragma unroll
    for (int o = 0; o < KD; o++) {
        float x = sw1[o*3]*g0 + sw1[o*3+1]*g1v + sw1[o*3+2]*g2v + sb1[o];
        float u = 0.7978845608028654f * (x + 0.044715f * x*x*x);
        h[o] = 0.5f * x * (1.f + tanhf(u));
    }
    float* op = proj + (size_t)b * KD * plane + pix;
    #pragma unroll
    for (int o = 0; o < KD; o++) {
        float s = sb2[o];
        #pragma unroll
        for (int k = 0; k < KD; k++) s += sw2[o*KD + k] * h[k];
        op[(size_t)o * plane] = s;
    }
}

// ---------------- tiled combined-kernel: softmax(range)*spatial, tap-major out ----------------
#define CTX 32
#define CTY 8
#define CHLX 38
#define CHLY 14
#define CITEMS (CHLX*CHLY)   // 532
__global__ void __launch_bounds__(256) comb_tiled_kernel(
        const float* __restrict__ proj,
        const float* __restrict__ rt_p, const float* __restrict__ sig_p,
        float* __restrict__ comb,
        int GH, int GW) {
    __shared__ float tile[2][CHLY][40];
    __shared__ int soff[CITEMS];
    int tid = threadIdx.x;
    int tx = tid % 32, ty = tid / 32;
    int x0 = blockIdx.x * CTX, y0 = blockIdx.y * CTY;
    int b = blockIdx.z;
    int x = x0 + tx, y = y0 + ty;
    int plane = GH * GW;

    for (int i = tid; i < CITEMS; i += 256) {
        int hy = i / CHLX, hx = i % CHLX;
        soff[i] = refl(y0 + hy - RAD, GH)*GW + refl(x0 + hx - RAD, GW);
    }
    __syncthreads();
    int so0 = soff[tid];
    int so1 = soff[tid + 256];
    int so2 = (tid < CITEMS - 512) ? soff[tid + 512] : 0;
    int r0 = tid / CHLX,        c0 = tid % CHLX;
    int r1 = (tid+256) / CHLX,  c1 = (tid+256) % CHLX;
    int r2 = (tid+512) / CHLX,  c2 = (tid+512) % CHLX;

    const float* pb_ = proj + (size_t)b * KD * plane;
    {
        const float* kp = pb_;
        tile[0][r0][c0] = __ldg(&kp[so0]);
        tile[0][r1][c1] = __ldg(&kp[so1]);
        if (tid < CITEMS - 512) tile[0][r2][c2] = __ldg(&kp[so2]);
    }
    __syncthreads();

    float l[NTAP];
    #pragma unroll
    for (int p = 0; p < NTAP; p++) l[p] = 0.f;

    for (int k = 0; k < KD; k++) {
        int cur = k & 1;
        float pf0 = 0.f, pf1 = 0.f, pf2 = 0.f;
        if (k + 1 < KD) {
            const float* kp = pb_ + (size_t)(k+1) * plane;
            pf0 = __ldg(&kp[so0]);
            pf1 = __ldg(&kp[so1]);
            if (tid < CITEMS - 512) pf2 = __ldg(&kp[so2]);
        }
        float cv = tile[cur][ty+RAD][tx+RAD];
        #pragma unroll
        for (int i = 0; i < DIAM; i++)
            #pragma unroll
            for (int j = 0; j < DIAM; j++)
                l[i*DIAM+j] += cv * tile[cur][ty+i][tx+j];
        if (k + 1 < KD) {
            tile[cur^1][r0][c0] = pf0;
            tile[cur^1][r1][c1] = pf1;
            if (tid < CITEMS - 512) tile[cur^1][r2][c2] = pf2;
        }
        __syncthreads();
    }

    float temp = expf(rt_p[0]);
    temp = fminf(fmaxf(temp, 1e-4f), 1e4f);
    float sig = sig_p[0];
    float inv2s2 = 1.f / (2.f * sig * sig);

    float m = -1e30f;
    #pragma unroll
    for (int p = 0; p < NTAP; p++) { l[p] *= temp; m = fmaxf(m, l[p]); }
    float Z = 0.f;
    #pragma unroll
    for (int p = 0; p < NTAP; p++) { l[p] = expf(l[p] - m); Z += l[p]; }
    float invZ = 1.f / Z;
    float S = 0.f;
    #pragma unroll
    for (int p = 0; p < NTAP; p++) {
        int i = p / DIAM, j = p % DIAM;
        float dy = (i - 3) * (1.f/3.f), dx = (j - 3) * (1.f/3.f);
        float sp = expf(-(dx*dx + dy*dy) * inv2s2);
        l[p] = (l[p] * invZ) * sp;
        S += l[p];
    }
    S = fmaxf(S, 1e-7f);
    float invS = 1.f / S;
    float* op = comb + (size_t)b * NTAP * plane + (size_t)y*GW + x;
    #pragma unroll
    for (int p = 0; p < NTAP; p++) op[(size_t)p * plane] = l[p] * invS;
}

// ---------------- bicubic weight helper ----------------
__device__ __forceinline__ float keysw(float x) {
    x = fabsf(x);
    if (x <= 1.f)      return ((1.5f*x - 2.5f)*x)*x + 1.f;
    else if (x < 2.f)  return ((-0.5f*x + 2.5f)*x - 4.f)*x + 2.f;
    return 0.f;
}
__device__ __forceinline__ void cubw(int o, int n, int* base, float w[4]) {
    float cc = 0.5f * o - 0.25f;
    int bb = (int)floorf(cc);
    float t = cc - (float)bb;
    w[0] = keysw(1.f + t); w[1] = keysw(t); w[2] = keysw(1.f - t); w[3] = keysw(2.f - t);
    float s = 0.f;
    #pragma unroll
    for (int k = 0; k < 4; k++) {
        int ii = bb - 1 + k;
        if (ii < 0 || ii >= n) w[k] = 0.f;
        s += w[k];
    }
    float inv = 1.f / s;
    #pragma unroll
    for (int k = 0; k < 4; k++) w[k] *= inv;
    *base = bb - 1;
}

// ---------------- FUSED bicubic 2x + adaptive 7x7 conv (R7 layout, unchanged) ----------------
#define TLX 32
#define TLY 8
#define HLX 38
#define HLY 14
#define SRCW 24
#define SRCH 12
#define NHIT (HLX*SRCH)
#define NVIT (HLX*HLY)
#define NSIT (SRCW*SRCH)
#define NCHI 8
#define XPITCH 9
#define YPITCH (HLX*XPITCH)

#define OFF_S2T   0
#define OFF_TMPH  2400
#define OFF_HRT   6240
#define OFF_WSM   11028
#define OFF_WXS   23572
#define OFF_CXS   23724
#define OFF_WYS   23876
#define OFF_RYS   23932
#define DSM_FLOATS 23988

__global__ void __launch_bounds__(256, 2) jbu_fused_kernel(
        const float* __restrict__ src, const float* __restrict__ comb,
        float* __restrict__ out, int H, int W, int do_round) {
    extern __shared__ float dsm[];
    float* s2t  = dsm + OFF_S2T;
    float* tmpH = dsm + OFF_TMPH;
    float* hrt  = dsm + OFF_HRT;
    float* wsm  = dsm + OFF_WSM;
    float* wxs  = dsm + OFF_WXS;
    int*   cxs  = (int*)(dsm + OFF_CXS);
    float* wys  = dsm + OFF_WYS;
    int*   rys  = (int*)(dsm + OFF_RYS);

    int GH = 2*H, GW = 2*W;
    int tid = threadIdx.x;
    int x0 = blockIdx.x * TLX, y0 = blockIdx.y * TLY;
    int b = blockIdx.z;
    int plane = GH * GW;
    int sx0 = x0/2 - 4, sy0 = y0/2 - 4;
    int HW = H * W;

    if (tid < HLX + HLY) {
        if (tid < HLX) {
            int l = tid;
            int gx = refl(x0 - RAD + l, GW);
            int base; float w[4]; cubw(gx, W, &base, w);
            #pragma unroll
            for (int k = 0; k < 4; k++) {
                cxs[l*4+k] = min(max(base + k, 0), W-1) - sx0;
                wxs[l*4+k] = w[k];
            }
        } else {
            int l = tid - HLX;
            int gy = refl(y0 - RAD + l, GH);
            int base; float w[4]; cubw(gy, H, &base, w);
            #pragma unroll
            for (int k = 0; k < 4; k++) {
                rys[l*4+k] = min(max(base + k, 0), H-1) - sy0;
                wys[l*4+k] = w[k];
            }
        }
    }

    {
        int wr = tid >> 5, wc = tid & 31;
        const float* cp = comb + (size_t)b * NTAP * plane + (size_t)(y0+wr)*GW + (x0+wc);
        #pragma unroll 7
        for (int p = 0; p < NTAP; p++)
            wsm[p*256 + tid] = __ldg(&cp[(size_t)p * plane]);
    }

    int ch = tid & 7;
    int g  = (tid >> 3) & 3;
    int r  = tid >> 5;

    int sr0 = tid / SRCW,        sc0 = tid % SRCW;
    int sr1 = (tid+256) / SRCW,  sc1 = (tid+256) % SRCW;
    int has1 = (tid + 256 < NSIT);
    size_t o0 = (size_t)min(max(sy0 + sr0, 0), H-1)*W + min(max(sx0 + sc0, 0), W-1);
    size_t o1 = (size_t)min(max(sy0 + sr1, 0), H-1)*W + min(max(sx0 + sc1, 0), W-1);

    int h0r = tid / HLX,        h0c = tid % HLX;
    int h1r = (tid+256) / HLX,  h1c = (tid+256) % HLX;
    int hHas1 = (tid < NHIT - 256);
    int v0r = h0r,              v0c = h0c;
    int v1r = h1r,              v1c = h1c;
    int v2r = (tid+512) / HLX,  v2c = (tid+512) % HLX;
    int vHas2 = (tid < NVIT - 512);

    const float* sp = src + (size_t)b * CH * HW;
    float* opx = out + (size_t)b * CH * plane + (size_t)(y0+r)*GW + (x0 + 8*g);

    __syncthreads();

    #pragma unroll
    for (int c8 = 0; c8 < NCHI; c8++) {
        const float* cp = sp + (size_t)c8 * HW;
        s2t[c8*300 + sr0*25 + sc0] = __ldg(&cp[o0]);
        if (has1) s2t[c8*300 + sr1*25 + sc1] = __ldg(&cp[o1]);
    }
    __syncthreads();

    for (int it = 0; it < CH/NCHI; it++) {
        int c = NCHI*it;
        int havepf = (it + 1 < CH/NCHI);
        float pf0[NCHI], pf1[NCHI];
        if (havepf) {
            const float* npb = sp + (size_t)(c + NCHI) * HW;
            #pragma unroll
            for (int c8 = 0; c8 < NCHI; c8++) {
                pf0[c8] = __ldg(&npb[(size_t)c8*HW + o0]);
                if (has1) pf1[c8] = __ldg(&npb[(size_t)c8*HW + o1]);
            }
        }

        #pragma unroll
        for (int c8 = 0; c8 < NCHI; c8++) {
            float* tb = tmpH + c8*480;
            const float* sb = s2t + c8*300;
            tb[h0r*40 + h0c] = wxs[h0c*4+0]*sb[h0r*25 + cxs[h0c*4+0]]
                             + wxs[h0c*4+1]*sb[h0r*25 + cxs[h0c*4+1]]
                             + wxs[h0c*4+2]*sb[h0r*25 + cxs[h0c*4+2]]
                             + wxs[h0c*4+3]*sb[h0r*25 + cxs[h0c*4+3]];
            if (hHas1)
                tb[h1r*40 + h1c] = wxs[h1c*4+0]*sb[h1r*25 + cxs[h1c*4+0]]
                                 + wxs[h1c*4+1]*sb[h1r*25 + cxs[h1c*4+1]]
                                 + wxs[h1c*4+2]*sb[h1r*25 + cxs[h1c*4+2]]
                                 + wxs[h1c*4+3]*sb[h1r*25 + cxs[h1c*4+3]];
        }
        __syncthreads();

        if (havepf) {
            #pragma unroll
            for (int c8 = 0; c8 < NCHI; c8++) {
                s2t[c8*300 + sr0*25 + sc0] = pf0[c8];
                if (has1) s2t[c8*300 + sr1*25 + sc1] = pf1[c8];
            }
        }

        #pragma unroll
        for (int c8 = 0; c8 < NCHI; c8++) {
            const float* tb = tmpH + c8*480;
            hrt[v0r*YPITCH + v0c*XPITCH + c8]
                = wys[v0r*4+0]*tb[rys[v0r*4+0]*40 + v0c]
                + wys[v0r*4+1]*tb[rys[v0r*4+1]*40 + v0c]
                + wys[v0r*4+2]*tb[rys[v0r*4+2]*40 + v0c]
                + wys[v0r*4+3]*tb[rys[v0r*4+3]*40 + v0c];
            hrt[v1r*YPITCH + v1c*XPITCH + c8]
                = wys[v1r*4+0]*tb[rys[v1r*4+0]*40 + v1c]
                + wys[v1r*4+1]*tb[rys[v1r*4+1]*40 + v1c]
                + wys[v1r*4+2]*tb[rys[v1r*4+2]*40 + v1c]
                + wys[v1r*4+3]*tb[rys[v1r*4+3]*40 + v1c];
            if (vHas2)
                hrt[v2r*YPITCH + v2c*XPITCH + c8]
                    = wys[v2r*4+0]*tb[rys[v2r*4+0]*40 + v2c]
                    + wys[v2r*4+1]*tb[rys[v2r*4+1]*40 + v2c]
                    + wys[v2r*4+2]*tb[rys[v2r*4+2]*40 + v2c]
                    + wys[v2r*4+3]*tb[rys[v2r*4+3]*40 + v2c];
        }
        __syncthreads();

        float acc[8];
        #pragma unroll
        for (int j = 0; j < 8; j++) acc[j] = 0.f;
        #pragma unroll
        for (int i = 0; i < DIAM; i++) {
            const float* rowb = hrt + (r+i)*YPITCH + (8*g)*XPITCH + ch;
            float a[14];
            #pragma unroll
            for (int m = 0; m < 14; m++) a[m] = rowb[m*XPITCH];
            #pragma unroll
            for (int pc = 0; pc < DIAM; pc++) {
                const float4* wp4 = (const float4*)&wsm[(i*7+pc)*256 + r*32 + 8*g];
                float4 w0 = wp4[0], w1 = wp4[1];
                acc[0] += w0.x*a[pc+0]; acc[1] += w0.y*a[pc+1];
                acc[2] += w0.z*a[pc+2]; acc[3] += w0.w*a[pc+3];
                acc[4] += w1.x*a[pc+4]; acc[5] += w1.y*a[pc+5];
                acc[6] += w1.z*a[pc+6]; acc[7] += w1.w*a[pc+7];
            }
        }
        if (do_round) {
            #pragma unroll
            for (int j = 0; j < 8; j++) acc[j] = __uint_as_float(f2tf32(acc[j]));
        }
        float* dst = &opx[(size_t)(c + ch) * plane];
        *(float4*)&dst[0] = make_float4(acc[0], acc[1], acc[2], acc[3]);
        *(float4*)&dst[4] = make_float4(acc[4], acc[5], acc[6], acc[7]);
        __syncthreads();
    }
}

// ---------------- tf32 mma.sync GEMM, full M=256 per CTA (B read once) ----------------
#define GBM 256
#define GBN 128
#define GBK 16
#define GNK (CH/GBK)   // 24
#define NSTG 3
#define GTHREADS 512
// dynamic smem: As 3*256*20 floats, Bs 3*16*136 floats
#define GA_STRIDE 20
#define GA_STAGE  (GBM*GA_STRIDE)      // 5120
#define GB_STRIDE 136
#define GB_STAGE  (GBK*GB_STRIDE)      // 2176
#define GB_BASE   (NSTG*GA_STAGE)      // 15360
#define GSM_FLOATS (GB_BASE + NSTG*GB_STAGE)   // 21888 -> 87552 B

__device__ __forceinline__ void mma_tf32(float c[4],
        uint32_t a0, uint32_t a1, uint32_t a2, uint32_t a3,
        uint32_t b0, uint32_t b1) {
    asm volatile(
        "mma.sync.aligned.m16n8k8.row.col.f32.tf32.tf32.f32 "
        "{%0,%1,%2,%3},{%4,%5,%6,%7},{%8,%9},{%0,%1,%2,%3};\n"
        : "+f"(c[0]), "+f"(c[1]), "+f"(c[2]), "+f"(c[3])
        : "r"(a0), "r"(a1), "r"(a2), "r"(a3), "r"(b0), "r"(b1));
}
#define CP_ASYNC16(dst, src) \
    asm volatile("cp.async.cg.shared.global [%0], [%1], 16;\n" :: "r"(dst), "l"(src))
#define CP_COMMIT() asm volatile("cp.async.commit_group;\n" ::)
#define CP_WAIT1()  asm volatile("cp.async.wait_group 1;\n" ::)

__global__ void __launch_bounds__(GTHREADS) gemm_tf32_kernel(
        const float* __restrict__ A, const float* __restrict__ Bmat,
        const float* __restrict__ bias, float* __restrict__ C, int N) {
    extern __shared__ float gsm[];
    float* As = gsm;            // As[s][row][20]
    float* Bs = gsm + GB_BASE;  // Bs[s][k][136]

    int tid = threadIdx.x;
    int warp = tid / 32, lane = tid % 32;
    int wm = warp / 4, wn = warp % 4;      // 4x4 warps: warp tile 64(M) x 32(N)
    int g = lane / 4, tig = lane % 4;
    int bx = blockIdx.x * GBN;
    const float* Bb = Bmat + (size_t)blockIdx.z * CH * N;
    float* Cb = C + (size_t)blockIdx.z * OUTC * N;

    float acc[4][4][4];
    #pragma unroll
    for (int mi = 0; mi < 4; mi++)
        #pragma unroll
        for (int ni = 0; ni < 4; ni++)
            #pragma unroll
            for (int q = 0; q < 4; q++) acc[mi][ni][q] = 0.f;

    // A tile 256x16 = 1024 float4: ids tid, tid+512
    int ar0 = tid >> 2,        ac0 = (tid & 3) << 2;
    int ar1 = (tid+512) >> 2,  ac1 = ac0;
    // B tile 16x128 = 512 float4: one per thread
    int br0 = tid >> 5,        bc0 = (tid & 31) << 2;

    const float* a0p = &A[(size_t)ar0*CH + ac0];
    const float* a1p = &A[(size_t)ar1*CH + ac1];
    const float* b0p = &Bb[(size_t)br0*N + bx + bc0];

    uint32_t sa0[NSTG], sa1[NSTG], sb0[NSTG];
    #pragma unroll
    for (int s = 0; s < NSTG; s++) {
        sa0[s] = (uint32_t)__cvta_generic_to_shared(&As[s*GA_STAGE + ar0*GA_STRIDE + ac0]);
        sa1[s] = (uint32_t)__cvta_generic_to_shared(&As[s*GA_STAGE + ar1*GA_STRIDE + ac1]);
        sb0[s] = (uint32_t)__cvta_generic_to_shared(&Bs[s*GB_STAGE + br0*GB_STRIDE + bc0]);
    }

    #pragma unroll
    for (int s = 0; s < 2; s++) {
        int k0 = s * GBK;
        CP_ASYNC16(sa0[s], a0p + k0);
        CP_ASYNC16(sa1[s], a1p + k0);
        CP_ASYNC16(sb0[s], b0p + (size_t)k0 * N);
        CP_COMMIT();
    }

    for (int kt = 0; kt < GNK; kt++) {
        int cur = kt % NSTG;
        CP_WAIT1();
        __syncthreads();
        if (kt + 2 < GNK) {
            int s = (kt + 2) % NSTG;
            int k0 = (kt + 2) * GBK;
            CP_ASYNC16(sa0[s], a0p + k0);
            CP_ASYNC16(sa1[s], a1p + k0);
            CP_ASYNC16(sb0[s], b0p + (size_t)k0 * N);
        }
        CP_COMMIT();

        const float* Ac = As + cur*GA_STAGE;
        const float* Bc = Bs + cur*GB_STAGE;
        #pragma unroll
        for (int ksub = 0; ksub < 2; ksub++) {
            int kb = ksub * 8;
            uint32_t af[4][4], bf[4][2];
            #pragma unroll
            for (int mi = 0; mi < 4; mi++) {
                int row = wm*64 + mi*16 + g;
                af[mi][0] = __float_as_uint(Ac[(row  )*GA_STRIDE + kb + tig]);
                af[mi][1] = __float_as_uint(Ac[(row+8)*GA_STRIDE + kb + tig]);
                af[mi][2] = __float_as_uint(Ac[(row  )*GA_STRIDE + kb + tig + 4]);
                af[mi][3] = __float_as_uint(Ac[(row+8)*GA_STRIDE + kb + tig + 4]);
            }
            #pragma unroll
            for (int ni = 0; ni < 4; ni++) {
                int col = wn*32 + ni*8 + g;
                bf[ni][0] = __float_as_uint(Bc[(kb + tig    )*GB_STRIDE + col]);
                bf[ni][1] = __float_as_uint(Bc[(kb + tig + 4)*GB_STRIDE + col]);
            }
            #pragma unroll
            for (int mi = 0; mi < 4; mi++)
                #pragma unroll
                for (int ni = 0; ni < 4; ni++)
                    mma_tf32(acc[mi][ni], af[mi][0], af[mi][1], af[mi][2], af[mi][3],
                             bf[ni][0], bf[ni][1]);
        }
    }

    #pragma unroll
    for (int mi = 0; mi < 4; mi++) {
        int r0 = wm*64 + mi*16 + g;
        float bi0 = bias[r0], bi1 = bias[r0 + 8];
        #pragma unroll
        for (int ni = 0; ni < 4; ni++) {
            int cc = bx + wn*32 + ni*8 + tig*2;
            *(float2*)&Cb[(size_t)r0*N + cc]     = make_float2(acc[mi][ni][0]+bi0, acc[mi][ni][1]+bi0);
            *(float2*)&Cb[(size_t)(r0+8)*N + cc] = make_float2(acc[mi][ni][2]+bi1, acc[mi][ni][3]+bi1);
        }
    }
}

// ---------------- host launch ----------------
extern "C" void kernel_launch(void* const* d_in, const int* in_sizes, int n_in,
                              void* d_out, int out_size) {
    const float* source   = (const float*)d_in[0];
    const float* guidance = (const float*)d_in[1];
    const float* u1w1 = (const float*)d_in[2];
    const float* u1b1 = (const float*)d_in[3];
    const float* u1w2 = (const float*)d_in[4];
    const float* u1b2 = (const float*)d_in[5];
    const float* u1rt = (const float*)d_in[6];
    const float* u1sg = (const float*)d_in[7];
    const float* u2w1 = (const float*)d_in[8];
    const float* u2b1 = (const float*)d_in[9];
    const float* u2w2 = (const float*)d_in[10];
    const float* u2b2 = (const float*)d_in[11];
    const float* u2rt = (const float*)d_in[12];
    const float* u2sg = (const float*)d_in[13];
    const float* fixw = (const float*)d_in[14];
    const float* fixb = (const float*)d_in[15];
    const float* prjw = (const float*)d_in[16];
    const float* prjb = (const float*)d_in[17];
    float* out = (float*)d_out;

    float *g1, *g2, *p1, *p2, *c1, *c2, *s2, *s4, *weff, *beff;
    cudaGetSymbolAddress((void**)&g1,  g_g1);
    cudaGetSymbolAddress((void**)&g2,  g_g2);
    cudaGetSymbolAddress((void**)&p1,  g_p1);
    cudaGetSymbolAddress((void**)&p2,  g_p2);
    cudaGetSymbolAddress((void**)&c1,  g_c1);
    cudaGetSymbolAddress((void**)&c2,  g_c2);
    cudaGetSymbolAddress((void**)&s2,  g_s2);
    cudaGetSymbolAddress((void**)&s4,  g_s4);
    cudaGetSymbolAddress((void**)&weff, g_weff);
    cudaGetSymbolAddress((void**)&beff, g_beff);

    const int dsm_bytes = DSM_FLOATS * 4;
    cudaFuncSetAttribute(jbu_fused_kernel,
                         cudaFuncAttributeMaxDynamicSharedMemorySize, dsm_bytes);
    const int gsm_bytes = GSM_FLOATS * 4;   // 87552
    cudaFuncSetAttribute(gemm_tf32_kernel,
                         cudaFuncAttributeMaxDynamicSharedMemorySize, gsm_bytes);

    weff_kernel<<<(OUTC*CH + 255)/256, 256>>>(prjw, prjb, fixw, fixb, weff, beff);

    pool_kernel<<<(BATCH*3*96*96   + 255)/256, 256>>>(guidance, g1, 96, 96, 8);
    pool_kernel<<<(BATCH*3*192*192 + 255)/256, 256>>>(guidance, g2, 192, 192, 4);

    // ---- stage 1: 48 -> 96 ----
    rproj_kernel<<<(BATCH*96*96 + 255)/256, 256>>>(g1, u1w1, u1b1, u1w2, u1b2, p1, 96, 96);
    comb_tiled_kernel<<<dim3(96/CTX, 96/CTY, BATCH), 256>>>(p1, u1rt, u1sg, c1, 96, 96);
    jbu_fused_kernel<<<dim3(96/TLX, 96/TLY, BATCH), 256, dsm_bytes>>>(source, c1, s2, 48, 48, 0);

    // ---- stage 2: 96 -> 192 ----
    rproj_kernel<<<(BATCH*192*192 + 255)/256, 256>>>(g2, u2w1, u2b1, u2w2, u2b2, p2, 192, 192);
    comb_tiled_kernel<<<dim3(192/CTX, 192/CTY, BATCH), 256>>>(p2, u2rt, u2sg, c2, 192, 192);
    jbu_fused_kernel<<<dim3(192/TLX, 192/TLY, BATCH), 256, dsm_bytes>>>(s2, c2, s4, 96, 96, 1);

    // ---- fused fixup+proj GEMM (tf32 mma.sync, full-M CTAs, B read once) ----
    gemm_tf32_kernel<<<dim3(192*192/GBN, 1, BATCH), GTHREADS, gsm_bytes>>>(weff, s4, beff, out, 192*192);
}

// round 13
// speedup vs baseline: 1.0713x; 1.0713x over previous
#include <cuda_runtime.h>
#include <math.h>
#include <stdint.h>

#define BATCH 8
#define CH    384
#define OUTC  256
#define KD    32
#define RAD   3
#define DIAM  7
#define NTAP  49

// ---------------- scratch ----------------
__device__ float g_g1  [BATCH*3*96*96];
__device__ float g_g2  [BATCH*3*192*192];
__device__ float g_p1  [BATCH*KD*96*96];
__device__ float g_p2  [BATCH*KD*192*192];
__device__ float g_c1  [BATCH*NTAP*96*96];
__device__ float g_c2  [BATCH*NTAP*192*192];
__device__ float g_s2  [(size_t)BATCH*CH*96*96];
__device__ float g_s4  [(size_t)BATCH*CH*192*192];
__device__ float g_weff[OUTC*CH];
__device__ float g_beff[OUTC];

__device__ __forceinline__ int refl(int i, int n) {
    if (i < 0) i = -i;
    if (i >= n) i = 2*n - 2 - i;
    return i;
}
__device__ __forceinline__ uint32_t f2tf32(float x) {
    uint32_t u;
    asm("cvt.rna.tf32.f32 %0, %1;" : "=r"(u) : "f"(x));
    return u;
}

// ---------------- W_eff = P + 0.1 P F ; b_eff = pb + 0.1 P fb (tf32-rounded W) ----------------
__global__ void weff_kernel(const float* __restrict__ Pw, const float* __restrict__ pb,
                            const float* __restrict__ Fw, const float* __restrict__ fb,
                            float* __restrict__ Weff, float* __restrict__ beff) {
    int idx = blockIdx.x * blockDim.x + threadIdx.x;
    if (idx < OUTC*CH) {
        int o = idx / CH, c = idx % CH;
        float acc = 0.f;
        #pragma unroll 4
        for (int k = 0; k < CH; k++) acc += Pw[o*CH + k] * Fw[k*CH + c];
        Weff[idx] = __uint_as_float(f2tf32(Pw[o*CH + c] + 0.1f * acc));
    }
    if (idx < OUTC) {
        float a = 0.f;
        for (int k = 0; k < CH; k++) a += Pw[idx*CH + k] * fb[k];
        beff[idx] = pb[idx] + 0.1f * a;
    }
}

// ---------------- adaptive avg pool ----------------
__global__ void pool_kernel(const float* __restrict__ g, float* __restrict__ out,
                            int OH, int OW, int F) {
    int idx = blockIdx.x * blockDim.x + threadIdx.x;
    int total = BATCH * 3 * OH * OW;
    if (idx >= total) return;
    int ox = idx % OW; int t = idx / OW;
    int oy = t % OH;   t /= OH;
    int c  = t % 3;    int b = t / 3;
    const float* p = g + (((size_t)(b*3 + c)*768) + (size_t)oy*F)*768 + (size_t)ox*F;
    float s = 0.f;
    for (int i = 0; i < F; i++)
        for (int j = 0; j < F; j++)
            s += p[i*768 + j];
    out[idx] = s / (float)(F*F);
}

// ---------------- range projection MLP: 3 -> 32 (gelu) -> 32, CHANNEL-major out ----------------
__global__ void rproj_kernel(const float* __restrict__ g,
                             const float* __restrict__ w1, const float* __restrict__ b1,
                             const float* __restrict__ w2, const float* __restrict__ b2,
                             float* __restrict__ proj, int GH, int GW) {
    __shared__ float sw1[KD*3], sb1[KD], sw2[KD*KD], sb2[KD];
    int tid = threadIdx.x;
    for (int i = tid; i < KD*3;  i += blockDim.x) sw1[i] = w1[i];
    for (int i = tid; i < KD;    i += blockDim.x) { sb1[i] = b1[i]; sb2[i] = b2[i]; }
    for (int i = tid; i < KD*KD; i += blockDim.x) sw2[i] = w2[i];
    __syncthreads();
    int idx = blockIdx.x * blockDim.x + tid;
    int plane = GH * GW;
    if (idx >= BATCH * plane) return;
    int b = idx / plane, pix = idx % plane;
    float g0 = g[(size_t)(b*3 + 0)*plane + pix];
    float g1v = g[(size_t)(b*3 + 1)*plane + pix];
    float g2v = g[(size_t)(b*3 + 2)*plane + pix];
    float h[KD];
    #pragma unroll
    for (int o = 0; o < KD; o++) {
        float x = sw1[o*3]*g0 + sw1[o*3+1]*g1v + sw1[o*3+2]*g2v + sb1[o];
        float u = 0.7978845608028654f * (x + 0.044715f * x*x*x);
        h[o] = 0.5f * x * (1.f + tanhf(u));
    }
    float* op = proj + (size_t)b * KD * plane + pix;
    #pragma unroll
    for (int o = 0; o < KD; o++) {
        float s = sb2[o];
        #pragma unroll
        for (int k = 0; k < KD; k++) s += sw2[o*KD + k] * h[k];
        op[(size_t)o * plane] = s;
    }
}

// ---------------- tiled combined-kernel: softmax(range)*spatial, tap-major out ----------------
#define CTX 32
#define CTY 8
#define CHLX 38
#define CHLY 14
#define CITEMS (CHLX*CHLY)   // 532
__global__ void __launch_bounds__(256) comb_tiled_kernel(
        const float* __restrict__ proj,
        const float* __restrict__ rt_p, const float* __restrict__ sig_p,
        float* __restrict__ comb,
        int GH, int GW) {
    __shared__ float tile[2][CHLY][40];
    __shared__ int soff[CITEMS];
    int tid = threadIdx.x;
    int tx = tid % 32, ty = tid / 32;
    int x0 = blockIdx.x * CTX, y0 = blockIdx.y * CTY;
    int b = blockIdx.z;
    int x = x0 + tx, y = y0 + ty;
    int plane = GH * GW;

    for (int i = tid; i < CITEMS; i += 256) {
        int hy = i / CHLX, hx = i % CHLX;
        soff[i] = refl(y0 + hy - RAD, GH)*GW + refl(x0 + hx - RAD, GW);
    }
    __syncthreads();
    int so0 = soff[tid];
    int so1 = soff[tid + 256];
    int so2 = (tid < CITEMS - 512) ? soff[tid + 512] : 0;
    int r0 = tid / CHLX,        c0 = tid % CHLX;
    int r1 = (tid+256) / CHLX,  c1 = (tid+256) % CHLX;
    int r2 = (tid+512) / CHLX,  c2 = (tid+512) % CHLX;

    const float* pb_ = proj + (size_t)b * KD * plane;
    {
        const float* kp = pb_;
        tile[0][r0][c0] = __ldg(&kp[so0]);
        tile[0][r1][c1] = __ldg(&kp[so1]);
        if (tid < CITEMS - 512) tile[0][r2][c2] = __ldg(&kp[so2]);
    }
    __syncthreads();

    float l[NTAP];
    #pragma unroll
    for (int p = 0; p < NTAP; p++) l[p] = 0.f;

    for (int k = 0; k < KD; k++) {
        int cur = k & 1;
        float pf0 = 0.f, pf1 = 0.f, pf2 = 0.f;
        if (k + 1 < KD) {
            const float* kp = pb_ + (size_t)(k+1) * plane;
            pf0 = __ldg(&kp[so0]);
            pf1 = __ldg(&kp[so1]);
            if (tid < CITEMS - 512) pf2 = __ldg(&kp[so2]);
        }
        float cv = tile[cur][ty+RAD][tx+RAD];
        #pragma unroll
        for (int i = 0; i < DIAM; i++)
            #pragma unroll
            for (int j = 0; j < DIAM; j++)
                l[i*DIAM+j] += cv * tile[cur][ty+i][tx+j];
        if (k + 1 < KD) {
            tile[cur^1][r0][c0] = pf0;
            tile[cur^1][r1][c1] = pf1;
            if (tid < CITEMS - 512) tile[cur^1][r2][c2] = pf2;
        }
        __syncthreads();
    }

    float temp = expf(rt_p[0]);
    temp = fminf(fmaxf(temp, 1e-4f), 1e4f);
    float sig = sig_p[0];
    float inv2s2 = 1.f / (2.f * sig * sig);

    float m = -1e30f;
    #pragma unroll
    for (int p = 0; p < NTAP; p++) { l[p] *= temp; m = fmaxf(m, l[p]); }
    float Z = 0.f;
    #pragma unroll
    for (int p = 0; p < NTAP; p++) { l[p] = expf(l[p] - m); Z += l[p]; }
    float invZ = 1.f / Z;
    float S = 0.f;
    #pragma unroll
    for (int p = 0; p < NTAP; p++) {
        int i = p / DIAM, j = p % DIAM;
        float dy = (i - 3) * (1.f/3.f), dx = (j - 3) * (1.f/3.f);
        float sp = expf(-(dx*dx + dy*dy) * inv2s2);
        l[p] = (l[p] * invZ) * sp;
        S += l[p];
    }
    S = fmaxf(S, 1e-7f);
    float invS = 1.f / S;
    float* op = comb + (size_t)b * NTAP * plane + (size_t)y*GW + x;
    #pragma unroll
    for (int p = 0; p < NTAP; p++) op[(size_t)p * plane] = l[p] * invS;
}

// ---------------- bicubic weight helper ----------------
__device__ __forceinline__ float keysw(float x) {
    x = fabsf(x);
    if (x <= 1.f)      return ((1.5f*x - 2.5f)*x)*x + 1.f;
    else if (x < 2.f)  return ((-0.5f*x + 2.5f)*x - 4.f)*x + 2.f;
    return 0.f;
}
__device__ __forceinline__ void cubw(int o, int n, int* base, float w[4]) {
    float cc = 0.5f * o - 0.25f;
    int bb = (int)floorf(cc);
    float t = cc - (float)bb;
    w[0] = keysw(1.f + t); w[1] = keysw(t); w[2] = keysw(1.f - t); w[3] = keysw(2.f - t);
    float s = 0.f;
    #pragma unroll
    for (int k = 0; k < 4; k++) {
        int ii = bb - 1 + k;
        if (ii < 0 || ii >= n) w[k] = 0.f;
        s += w[k];
    }
    float inv = 1.f / s;
    #pragma unroll
    for (int k = 0; k < 4; k++) w[k] *= inv;
    *base = bb - 1;
}

// ---------------- FUSED bicubic 2x + adaptive 7x7 conv (R7 layout) ----------------
#define TLX 32
#define TLY 8
#define HLX 38
#define HLY 14
#define SRCW 24
#define SRCH 12
#define NHIT (HLX*SRCH)
#define NVIT (HLX*HLY)
#define NSIT (SRCW*SRCH)
#define NCHI 8
#define XPITCH 9
#define YPITCH (HLX*XPITCH)

#define OFF_S2T   0
#define OFF_TMPH  2400
#define OFF_HRT   6240
#define OFF_WSM   11028
#define OFF_WXS   23572
#define OFF_CXS   23724
#define OFF_WYS   23876
#define OFF_RYS   23932
#define DSM_FLOATS 23988

__global__ void __launch_bounds__(256, 2) jbu_fused_kernel(
        const float* __restrict__ src, const float* __restrict__ comb,
        float* __restrict__ out, int H, int W, int do_round) {
    extern __shared__ float dsm[];
    float* s2t  = dsm + OFF_S2T;
    float* tmpH = dsm + OFF_TMPH;
    float* hrt  = dsm + OFF_HRT;
    float* wsm  = dsm + OFF_WSM;
    float* wxs  = dsm + OFF_WXS;
    int*   cxs  = (int*)(dsm + OFF_CXS);
    float* wys  = dsm + OFF_WYS;
    int*   rys  = (int*)(dsm + OFF_RYS);

    int GH = 2*H, GW = 2*W;
    int tid = threadIdx.x;
    int x0 = blockIdx.x * TLX, y0 = blockIdx.y * TLY;
    int b = blockIdx.z;
    int plane = GH * GW;
    int sx0 = x0/2 - 4, sy0 = y0/2 - 4;
    int HW = H * W;

    if (tid < HLX + HLY) {
        if (tid < HLX) {
            int l = tid;
            int gx = refl(x0 - RAD + l, GW);
            int base; float w[4]; cubw(gx, W, &base, w);
            #pragma unroll
            for (int k = 0; k < 4; k++) {
                cxs[l*4+k] = min(max(base + k, 0), W-1) - sx0;
                wxs[l*4+k] = w[k];
            }
        } else {
            int l = tid - HLX;
            int gy = refl(y0 - RAD + l, GH);
            int base; float w[4]; cubw(gy, H, &base, w);
            #pragma unroll
            for (int k = 0; k < 4; k++) {
                rys[l*4+k] = min(max(base + k, 0), H-1) - sy0;
                wys[l*4+k] = w[k];
            }
        }
    }

    {
        int wr = tid >> 5, wc = tid & 31;
        const float* cp = comb + (size_t)b * NTAP * plane + (size_t)(y0+wr)*GW + (x0+wc);
        #pragma unroll 7
        for (int p = 0; p < NTAP; p++)
            wsm[p*256 + tid] = __ldg(&cp[(size_t)p * plane]);
    }

    int ch = tid & 7;
    int g  = (tid >> 3) & 3;
    int r  = tid >> 5;

    int sr0 = tid / SRCW,        sc0 = tid % SRCW;
    int sr1 = (tid+256) / SRCW,  sc1 = (tid+256) % SRCW;
    int has1 = (tid + 256 < NSIT);
    size_t o0 = (size_t)min(max(sy0 + sr0, 0), H-1)*W + min(max(sx0 + sc0, 0), W-1);
    size_t o1 = (size_t)min(max(sy0 + sr1, 0), H-1)*W + min(max(sx0 + sc1, 0), W-1);

    int h0r = tid / HLX,        h0c = tid % HLX;
    int h1r = (tid+256) / HLX,  h1c = (tid+256) % HLX;
    int hHas1 = (tid < NHIT - 256);
    int v0r = h0r,              v0c = h0c;
    int v1r = h1r,              v1c = h1c;
    int v2r = (tid+512) / HLX,  v2c = (tid+512) % HLX;
    int vHas2 = (tid < NVIT - 512);

    const float* sp = src + (size_t)b * CH * HW;
    float* opx = out + (size_t)b * CH * plane + (size_t)(y0+r)*GW + (x0 + 8*g);

    __syncthreads();

    #pragma unroll
    for (int c8 = 0; c8 < NCHI; c8++) {
        const float* cp = sp + (size_t)c8 * HW;
        s2t[c8*300 + sr0*25 + sc0] = __ldg(&cp[o0]);
        if (has1) s2t[c8*300 + sr1*25 + sc1] = __ldg(&cp[o1]);
    }
    __syncthreads();

    for (int it = 0; it < CH/NCHI; it++) {
        int c = NCHI*it;
        int havepf = (it + 1 < CH/NCHI);
        float pf0[NCHI], pf1[NCHI];
        if (havepf) {
            const float* npb = sp + (size_t)(c + NCHI) * HW;
            #pragma unroll
            for (int c8 = 0; c8 < NCHI; c8++) {
                pf0[c8] = __ldg(&npb[(size_t)c8*HW + o0]);
                if (has1) pf1[c8] = __ldg(&npb[(size_t)c8*HW + o1]);
            }
        }

        #pragma unroll
        for (int c8 = 0; c8 < NCHI; c8++) {
            float* tb = tmpH + c8*480;
            const float* sb = s2t + c8*300;
            tb[h0r*40 + h0c] = wxs[h0c*4+0]*sb[h0r*25 + cxs[h0c*4+0]]
                             + wxs[h0c*4+1]*sb[h0r*25 + cxs[h0c*4+1]]
                             + wxs[h0c*4+2]*sb[h0r*25 + cxs[h0c*4+2]]
                             + wxs[h0c*4+3]*sb[h0r*25 + cxs[h0c*4+3]];
            if (hHas1)
                tb[h1r*40 + h1c] = wxs[h1c*4+0]*sb[h1r*25 + cxs[h1c*4+0]]
                                 + wxs[h1c*4+1]*sb[h1r*25 + cxs[h1c*4+1]]
                                 + wxs[h1c*4+2]*sb[h1r*25 + cxs[h1c*4+2]]
                                 + wxs[h1c*4+3]*sb[h1r*25 + cxs[h1c*4+3]];
        }
        __syncthreads();

        if (havepf) {
            #pragma unroll
            for (int c8 = 0; c8 < NCHI; c8++) {
                s2t[c8*300 + sr0*25 + sc0] = pf0[c8];
                if (has1) s2t[c8*300 + sr1*25 + sc1] = pf1[c8];
            }
        }

        #pragma unroll
        for (int c8 = 0; c8 < NCHI; c8++) {
            const float* tb = tmpH + c8*480;
            hrt[v0r*YPITCH + v0c*XPITCH + c8]
                = wys[v0r*4+0]*tb[rys[v0r*4+0]*40 + v0c]
                + wys[v0r*4+1]*tb[rys[v0r*4+1]*40 + v0c]
                + wys[v0r*4+2]*tb[rys[v0r*4+2]*40 + v0c]
                + wys[v0r*4+3]*tb[rys[v0r*4+3]*40 + v0c];
            hrt[v1r*YPITCH + v1c*XPITCH + c8]
                = wys[v1r*4+0]*tb[rys[v1r*4+0]*40 + v1c]
                + wys[v1r*4+1]*tb[rys[v1r*4+1]*40 + v1c]
                + wys[v1r*4+2]*tb[rys[v1r*4+2]*40 + v1c]
                + wys[v1r*4+3]*tb[rys[v1r*4+3]*40 + v1c];
            if (vHas2)
                hrt[v2r*YPITCH + v2c*XPITCH + c8]
                    = wys[v2r*4+0]*tb[rys[v2r*4+0]*40 + v2c]
                    + wys[v2r*4+1]*tb[rys[v2r*4+1]*40 + v2c]
                    + wys[v2r*4+2]*tb[rys[v2r*4+2]*40 + v2c]
                    + wys[v2r*4+3]*tb[rys[v2r*4+3]*40 + v2c];
        }
        __syncthreads();

        float acc[8];
        #pragma unroll
        for (int j = 0; j < 8; j++) acc[j] = 0.f;
        #pragma unroll
        for (int i = 0; i < DIAM; i++) {
            const float* rowb = hrt + (r+i)*YPITCH + (8*g)*XPITCH + ch;
            float a[14];
            #pragma unroll
            for (int m = 0; m < 14; m++) a[m] = rowb[m*XPITCH];
            #pragma unroll
            for (int pc = 0; pc < DIAM; pc++) {
                const float4* wp4 = (const float4*)&wsm[(i*7+pc)*256 + r*32 + 8*g];
                float4 w0 = wp4[0], w1 = wp4[1];
                acc[0] += w0.x*a[pc+0]; acc[1] += w0.y*a[pc+1];
                acc[2] += w0.z*a[pc+2]; acc[3] += w0.w*a[pc+3];
                acc[4] += w1.x*a[pc+4]; acc[5] += w1.y*a[pc+5];
                acc[6] += w1.z*a[pc+6]; acc[7] += w1.w*a[pc+7];
            }
        }
        if (do_round) {
            #pragma unroll
            for (int j = 0; j < 8; j++) acc[j] = __uint_as_float(f2tf32(acc[j]));
        }
        float* dst = &opx[(size_t)(c + ch) * plane];
        *(float4*)&dst[0] = make_float4(acc[0], acc[1], acc[2], acc[3]);
        *(float4*)&dst[4] = make_float4(acc[4], acc[5], acc[6], acc[7]);
        __syncthreads();
    }
}

// ---------------- tf32 tensor-core GEMM (R7 proven config: 128x128, 256 thr) ----------------
#define GBM 128
#define GBN 128
#define GBK 16
#define GNK (CH/GBK)   // 24
#define NSTG 3

__device__ __forceinline__ void mma_tf32(float c[4],
        uint32_t a0, uint32_t a1, uint32_t a2, uint32_t a3,
        uint32_t b0, uint32_t b1) {
    asm volatile(
        "mma.sync.aligned.m16n8k8.row.col.f32.tf32.tf32.f32 "
        "{%0,%1,%2,%3},{%4,%5,%6,%7},{%8,%9},{%0,%1,%2,%3};\n"
        : "+f"(c[0]), "+f"(c[1]), "+f"(c[2]), "+f"(c[3])
        : "r"(a0), "r"(a1), "r"(a2), "r"(a3), "r"(b0), "r"(b1));
}
#define CP_ASYNC16(dst, src) \
    asm volatile("cp.async.cg.shared.global [%0], [%1], 16;\n" :: "r"(dst), "l"(src))
#define CP_COMMIT() asm volatile("cp.async.commit_group;\n" ::)
#define CP_WAIT1()  asm volatile("cp.async.wait_group 1;\n" ::)

__global__ void __launch_bounds__(256) gemm_tf32_kernel(
        const float* __restrict__ A, const float* __restrict__ Bmat,
        const float* __restrict__ bias, float* __restrict__ C, int N) {
    __shared__ float As[NSTG][GBM][20];
    __shared__ float Bs[NSTG][GBK][136];

    int tid = threadIdx.x;
    int warp = tid / 32, lane = tid % 32;
    int wm = warp / 4, wn = warp % 4;
    int g = lane / 4, tig = lane % 4;
    int bx = blockIdx.x * GBN, by = blockIdx.y * GBM;
    const float* Bb = Bmat + (size_t)blockIdx.z * CH * N;
    float* Cb = C + (size_t)blockIdx.z * OUTC * N;

    float acc[4][4][4];
    #pragma unroll
    for (int mi = 0; mi < 4; mi++)
        #pragma unroll
        for (int ni = 0; ni < 4; ni++)
            #pragma unroll
            for (int q = 0; q < 4; q++) acc[mi][ni][q] = 0.f;

    int ar0 = tid >> 2,        ac0 = (tid & 3) << 2;
    int ar1 = (tid+256) >> 2,  ac1 = ac0;
    int br0 = tid >> 5,        bc0 = (tid & 31) << 2;
    int br1 = (tid+256) >> 5,  bc1 = bc0;

    const float* a0p = &A[(size_t)(by + ar0)*CH + ac0];
    const float* a1p = &A[(size_t)(by + ar1)*CH + ac1];
    const float* b0p = &Bb[(size_t)br0*N + bx + bc0];
    const float* b1p = &Bb[(size_t)br1*N + bx + bc1];

    uint32_t sa0[NSTG], sa1[NSTG], sb0[NSTG], sb1[NSTG];
    #pragma unroll
    for (int s = 0; s < NSTG; s++) {
        sa0[s] = (uint32_t)__cvta_generic_to_shared(&As[s][ar0][ac0]);
        sa1[s] = (uint32_t)__cvta_generic_to_shared(&As[s][ar1][ac1]);
        sb0[s] = (uint32_t)__cvta_generic_to_shared(&Bs[s][br0][bc0]);
        sb1[s] = (uint32_t)__cvta_generic_to_shared(&Bs[s][br1][bc1]);
    }

    #pragma unroll
    for (int s = 0; s < 2; s++) {
        int k0 = s * GBK;
        CP_ASYNC16(sa0[s], a0p + k0);
        CP_ASYNC16(sa1[s], a1p + k0);
        CP_ASYNC16(sb0[s], b0p + (size_t)k0 * N);
        CP_ASYNC16(sb1[s], b1p + (size_t)k0 * N);
        CP_COMMIT();
    }

    for (int kt = 0; kt < GNK; kt++) {
        int cur = kt % NSTG;
        CP_WAIT1();
        __syncthreads();
        if (kt + 2 < GNK) {
            int s = (kt + 2) % NSTG;
            int k0 = (kt + 2) * GBK;
            CP_ASYNC16(sa0[s], a0p + k0);
            CP_ASYNC16(sa1[s], a1p + k0);
            CP_ASYNC16(sb0[s], b0p + (size_t)k0 * N);
            CP_ASYNC16(sb1[s], b1p + (size_t)k0 * N);
        }
        CP_COMMIT();

        #pragma unroll
        for (int ksub = 0; ksub < 2; ksub++) {
            int kb = ksub * 8;
            uint32_t af[4][4], bf[4][2];
            #pragma unroll
            for (int mi = 0; mi < 4; mi++) {
                int row = wm*64 + mi*16 + g;
                af[mi][0] = __float_as_uint(As[cur][row  ][kb + tig]);
                af[mi][1] = __float_as_uint(As[cur][row+8][kb + tig]);
                af[mi][2] = __float_as_uint(As[cur][row  ][kb + tig + 4]);
                af[mi][3] = __float_as_uint(As[cur][row+8][kb + tig + 4]);
            }
            #pragma unroll
            for (int ni = 0; ni < 4; ni++) {
                int col = wn*32 + ni*8 + g;
                bf[ni][0] = __float_as_uint(Bs[cur][kb + tig    ][col]);
                bf[ni][1] = __float_as_uint(Bs[cur][kb + tig + 4][col]);
            }
            #pragma unroll
            for (int mi = 0; mi < 4; mi++)
                #pragma unroll
                for (int ni = 0; ni < 4; ni++)
                    mma_tf32(acc[mi][ni], af[mi][0], af[mi][1], af[mi][2], af[mi][3],
                             bf[ni][0], bf[ni][1]);
        }
    }

    #pragma unroll
    for (int mi = 0; mi < 4; mi++) {
        int r0 = by + wm*64 + mi*16 + g;
        float bi0 = bias[r0], bi1 = bias[r0 + 8];
        #pragma unroll
        for (int ni = 0; ni < 4; ni++) {
            int cc = bx + wn*32 + ni*8 + tig*2;
            *(float2*)&Cb[(size_t)r0*N + cc]     = make_float2(acc[mi][ni][0]+bi0, acc[mi][ni][1]+bi0);
            *(float2*)&Cb[(size_t)(r0+8)*N + cc] = make_float2(acc[mi][ni][2]+bi1, acc[mi][ni][3]+bi1);
        }
    }
}

// ---------------- host launch: fork stage-2 prep onto a side stream ----------------
extern "C" void kernel_launch(void* const* d_in, const int* in_sizes, int n_in,
                              void* d_out, int out_size) {
    const float* source   = (const float*)d_in[0];
    const float* guidance = (const float*)d_in[1];
    const float* u1w1 = (const float*)d_in[2];
    const float* u1b1 = (const float*)d_in[3];
    const float* u1w2 = (const float*)d_in[4];
    const float* u1b2 = (const float*)d_in[5];
    const float* u1rt = (const float*)d_in[6];
    const float* u1sg = (const float*)d_in[7];
    const float* u2w1 = (const float*)d_in[8];
    const float* u2b1 = (const float*)d_in[9];
    const float* u2w2 = (const float*)d_in[10];
    const float* u2b2 = (const float*)d_in[11];
    const float* u2rt = (const float*)d_in[12];
    const float* u2sg = (const float*)d_in[13];
    const float* fixw = (const float*)d_in[14];
    const float* fixb = (const float*)d_in[15];
    const float* prjw = (const float*)d_in[16];
    const float* prjb = (const float*)d_in[17];
    float* out = (float*)d_out;

    float *g1, *g2, *p1, *p2, *c1, *c2, *s2, *s4, *weff, *beff;
    cudaGetSymbolAddress((void**)&g1,  g_g1);
    cudaGetSymbolAddress((void**)&g2,  g_g2);
    cudaGetSymbolAddress((void**)&p1,  g_p1);
    cudaGetSymbolAddress((void**)&p2,  g_p2);
    cudaGetSymbolAddress((void**)&c1,  g_c1);
    cudaGetSymbolAddress((void**)&c2,  g_c2);
    cudaGetSymbolAddress((void**)&s2,  g_s2);
    cudaGetSymbolAddress((void**)&s4,  g_s4);
    cudaGetSymbolAddress((void**)&weff, g_weff);
    cudaGetSymbolAddress((void**)&beff, g_beff);

    const int dsm_bytes = DSM_FLOATS * 4;
    cudaFuncSetAttribute(jbu_fused_kernel,
                         cudaFuncAttributeMaxDynamicSharedMemorySize, dsm_bytes);

    // side stream + fork/join events, created once on the first (uncaptured) call
    static cudaStream_t sB = (cudaStream_t)0;
    static cudaEvent_t evFork = (cudaEvent_t)0, evJoin = (cudaEvent_t)0;
    static int sInit = 0;
    if (!sInit) {
        sInit = 1;
        if (cudaStreamCreateWithFlags(&sB, cudaStreamNonBlocking) != cudaSuccess) sB = (cudaStream_t)0;
        if (cudaEventCreateWithFlags(&evFork, cudaEventDisableTiming) != cudaSuccess) evFork = (cudaEvent_t)0;
        if (cudaEventCreateWithFlags(&evJoin, cudaEventDisableTiming) != cudaSuccess) evJoin = (cudaEvent_t)0;
    }
    bool fork = (sB != (cudaStream_t)0) && (evFork != (cudaEvent_t)0) && (evJoin != (cudaEvent_t)0);
    cudaStream_t s2strm = fork ? sB : (cudaStream_t)0;

    if (fork) {
        cudaEventRecord(evFork, (cudaStream_t)0);
        cudaStreamWaitEvent(sB, evFork, 0);
    }

    // ---- branch B (side stream): stage-2 prep ----
    pool_kernel<<<(BATCH*3*192*192 + 255)/256, 256, 0, s2strm>>>(guidance, g2, 192, 192, 4);
    rproj_kernel<<<(BATCH*192*192 + 255)/256, 256, 0, s2strm>>>(g2, u2w1, u2b1, u2w2, u2b2, p2, 192, 192);
    comb_tiled_kernel<<<dim3(192/CTX, 192/CTY, BATCH), 256, 0, s2strm>>>(p2, u2rt, u2sg, c2, 192, 192);
    if (fork) cudaEventRecord(evJoin, sB);

    // ---- branch A (main stream): weff + stage-1 chain ----
    weff_kernel<<<(OUTC*CH + 255)/256, 256>>>(prjw, prjb, fixw, fixb, weff, beff);
    pool_kernel<<<(BATCH*3*96*96 + 255)/256, 256>>>(guidance, g1, 96, 96, 8);
    rproj_kernel<<<(BATCH*96*96 + 255)/256, 256>>>(g1, u1w1, u1b1, u1w2, u1b2, p1, 96, 96);
    comb_tiled_kernel<<<dim3(96/CTX, 96/CTY, BATCH), 256>>>(p1, u1rt, u1sg, c1, 96, 96);
    jbu_fused_kernel<<<dim3(96/TLX, 96/TLY, BATCH), 256, dsm_bytes>>>(source, c1, s2, 48, 48, 0);

    // ---- join, then stage-2 jbu + GEMM on main stream ----
    if (fork) cudaStreamWaitEvent((cudaStream_t)0, evJoin, 0);
    jbu_fused_kernel<<<dim3(192/TLX, 192/TLY, BATCH), 256, dsm_bytes>>>(s2, c2, s4, 96, 96, 1);
    gemm_tf32_kernel<<<dim3(192*192/GBN, OUTC/GBM, BATCH), 256>>>(weff, s4, beff, out, 192*192);
}

// round 15
// speedup vs baseline: 1.0798x; 1.0079x over previous
#include <cuda_runtime.h>
#include <math.h>
#include <stdint.h>

#define BATCH 8
#define CH    384
#define OUTC  256
#define KD    32
#define RAD   3
#define DIAM  7
#define NTAP  49

// ---------------- scratch ----------------
__device__ float g_g1  [BATCH*3*96*96];
__device__ float g_g2  [BATCH*3*192*192];
__device__ float g_p1  [BATCH*KD*96*96];
__device__ float g_p2  [BATCH*KD*192*192];
__device__ float g_c1  [BATCH*NTAP*96*96];
__device__ float g_c2  [BATCH*NTAP*192*192];
__device__ float g_s2  [(size_t)BATCH*CH*96*96];
__device__ float g_s4  [(size_t)BATCH*CH*192*192];
__device__ float g_weff[OUTC*CH];
__device__ float g_beff[OUTC];

__device__ __forceinline__ int refl(int i, int n) {
    if (i < 0) i = -i;
    if (i >= n) i = 2*n - 2 - i;
    return i;
}
__device__ __forceinline__ uint32_t f2tf32(float x) {
    uint32_t u;
    asm("cvt.rna.tf32.f32 %0, %1;" : "=r"(u) : "f"(x));
    return u;
}

// ---------------- FAST W_eff: tiled mini-GEMM (64x64 tiles, 4x4/thread) ----------------
#define WTM 64
#define WTN 64
#define WTK 16
__global__ void __launch_bounds__(256) weff_kernel(
        const float* __restrict__ Pw, const float* __restrict__ pb,
        const float* __restrict__ Fw, const float* __restrict__ fb,
        float* __restrict__ Weff, float* __restrict__ beff) {
    __shared__ float Ps[WTK][WTM+1];   // [k][o]
    __shared__ float Fs[WTK][WTN+1];   // [k][c]
    int tid = threadIdx.x;
    int tx = tid & 15, ty = tid >> 4;  // 16x16
    int o0 = blockIdx.y * WTM, c0 = blockIdx.x * WTN;

    float acc[4][4];
    #pragma unroll
    for (int m = 0; m < 4; m++)
        #pragma unroll
        for (int n = 0; n < 4; n++) acc[m][n] = 0.f;

    for (int k0 = 0; k0 < CH; k0 += WTK) {
        #pragma unroll
        for (int q = 0; q < 4; q++) {
            int i = tid + q*256;                  // 1024 items: 64 o x 16 k
            int o = i >> 4, k = i & 15;
            Ps[k][o] = Pw[(size_t)(o0 + o)*CH + k0 + k];
        }
        #pragma unroll
        for (int q = 0; q < 4; q++) {
            int i = tid + q*256;                  // 1024 items: 16 k x 64 c
            int k = i >> 6, c = i & 63;
            Fs[k][c] = Fw[(size_t)(k0 + k)*CH + c0 + c];
        }
        __syncthreads();
        #pragma unroll
        for (int k = 0; k < WTK; k++) {
            float a[4], bvec[4];
            #pragma unroll
            for (int m = 0; m < 4; m++) a[m] = Ps[k][ty*4 + m];
            #pragma unroll
            for (int n = 0; n < 4; n++) bvec[n] = Fs[k][tx*4 + n];
            #pragma unroll
            for (int m = 0; m < 4; m++)
                #pragma unroll
                for (int n = 0; n < 4; n++)
                    acc[m][n] += a[m] * bvec[n];
        }
        __syncthreads();
    }

    #pragma unroll
    for (int m = 0; m < 4; m++) {
        int o = o0 + ty*4 + m;
        #pragma unroll
        for (int n = 0; n < 4; n++) {
            int c = c0 + tx*4 + n;
            Weff[(size_t)o*CH + c] =
                __uint_as_float(f2tf32(Pw[(size_t)o*CH + c] + 0.1f * acc[m][n]));
        }
    }
    // beff by block (0,0): one output per thread (OUTC==256==blockDim)
    if (blockIdx.x == 0 && blockIdx.y == 0) {
        float a = 0.f;
        #pragma unroll 4
        for (int k = 0; k < CH; k++) a += Pw[(size_t)tid*CH + k] * fb[k];
        beff[tid] = pb[tid] + 0.1f * a;
    }
}

// ---------------- adaptive avg pool ----------------
__global__ void pool_kernel(const float* __restrict__ g, float* __restrict__ out,
                            int OH, int OW, int F) {
    int idx = blockIdx.x * blockDim.x + threadIdx.x;
    int total = BATCH * 3 * OH * OW;
    if (idx >= total) return;
    int ox = idx % OW; int t = idx / OW;
    int oy = t % OH;   t /= OH;
    int c  = t % 3;    int b = t / 3;
    const float* p = g + (((size_t)(b*3 + c)*768) + (size_t)oy*F)*768 + (size_t)ox*F;
    float s = 0.f;
    for (int i = 0; i < F; i++)
        for (int j = 0; j < F; j++)
            s += p[i*768 + j];
    out[idx] = s / (float)(F*F);
}

// ---------------- range projection MLP: 3 -> 32 (gelu) -> 32, CHANNEL-major out ----------------
__global__ void rproj_kernel(const float* __restrict__ g,
                             const float* __restrict__ w1, const float* __restrict__ b1,
                             const float* __restrict__ w2, const float* __restrict__ b2,
                             float* __restrict__ proj, int GH, int GW) {
    __shared__ float sw1[KD*3], sb1[KD], sw2[KD*KD], sb2[KD];
    int tid = threadIdx.x;
    for (int i = tid; i < KD*3;  i += blockDim.x) sw1[i] = w1[i];
    for (int i = tid; i < KD;    i += blockDim.x) { sb1[i] = b1[i]; sb2[i] = b2[i]; }
    for (int i = tid; i < KD*KD; i += blockDim.x) sw2[i] = w2[i];
    __syncthreads();
    int idx = blockIdx.x * blockDim.x + tid;
    int plane = GH * GW;
    if (idx >= BATCH * plane) return;
    int b = idx / plane, pix = idx % plane;
    float g0 = g[(size_t)(b*3 + 0)*plane + pix];
    float g1v = g[(size_t)(b*3 + 1)*plane + pix];
    float g2v = g[(size_t)(b*3 + 2)*plane + pix];
    float h[KD];
    #pragma unroll
    for (int o = 0; o < KD; o++) {
        float x = sw1[o*3]*g0 + sw1[o*3+1]*g1v + sw1[o*3+2]*g2v + sb1[o];
        float u = 0.7978845608028654f * (x + 0.044715f * x*x*x);
        h[o] = 0.5f * x * (1.f + tanhf(u));
    }
    float* op = proj + (size_t)b * KD * plane + pix;
    #pragma unroll
    for (int o = 0; o < KD; o++) {
        float s = sb2[o];
        #pragma unroll
        for (int k = 0; k < KD; k++) s += sw2[o*KD + k] * h[k];
        op[(size_t)o * plane] = s;
    }
}

// ---------------- tiled combined-kernel: softmax(range)*spatial, tap-major out ----------------
#define CTX 32
#define CTY 8
#define CHLX 38
#define CHLY 14
#define CITEMS (CHLX*CHLY)   // 532
__global__ void __launch_bounds__(256) comb_tiled_kernel(
        const float* __restrict__ proj,
        const float* __restrict__ rt_p, const float* __restrict__ sig_p,
        float* __restrict__ comb,
        int GH, int GW) {
    __shared__ float tile[2][CHLY][40];
    __shared__ int soff[CITEMS];
    int tid = threadIdx.x;
    int tx = tid % 32, ty = tid / 32;
    int x0 = blockIdx.x * CTX, y0 = blockIdx.y * CTY;
    int b = blockIdx.z;
    int x = x0 + tx, y = y0 + ty;
    int plane = GH * GW;

    for (int i = tid; i < CITEMS; i += 256) {
        int hy = i / CHLX, hx = i % CHLX;
        soff[i] = refl(y0 + hy - RAD, GH)*GW + refl(x0 + hx - RAD, GW);
    }
    __syncthreads();
    int so0 = soff[tid];
    int so1 = soff[tid + 256];
    int so2 = (tid < CITEMS - 512) ? soff[tid + 512] : 0;
    int r0 = tid / CHLX,        c0 = tid % CHLX;
    int r1 = (tid+256) / CHLX,  c1 = (tid+256) % CHLX;
    int r2 = (tid+512) / CHLX,  c2 = (tid+512) % CHLX;

    const float* pb_ = proj + (size_t)b * KD * plane;
    {
        const float* kp = pb_;
        tile[0][r0][c0] = __ldg(&kp[so0]);
        tile[0][r1][c1] = __ldg(&kp[so1]);
        if (tid < CITEMS - 512) tile[0][r2][c2] = __ldg(&kp[so2]);
    }
    __syncthreads();

    float l[NTAP];
    #pragma unroll
    for (int p = 0; p < NTAP; p++) l[p] = 0.f;

    for (int k = 0; k < KD; k++) {
        int cur = k & 1;
        float pf0 = 0.f, pf1 = 0.f, pf2 = 0.f;
        if (k + 1 < KD) {
            const float* kp = pb_ + (size_t)(k+1) * plane;
            pf0 = __ldg(&kp[so0]);
            pf1 = __ldg(&kp[so1]);
            if (tid < CITEMS - 512) pf2 = __ldg(&kp[so2]);
        }
        float cv = tile[cur][ty+RAD][tx+RAD];
        #pragma unroll
        for (int i = 0; i < DIAM; i++)
            #pragma unroll
            for (int j = 0; j < DIAM; j++)
                l[i*DIAM+j] += cv * tile[cur][ty+i][tx+j];
        if (k + 1 < KD) {
            tile[cur^1][r0][c0] = pf0;
            tile[cur^1][r1][c1] = pf1;
            if (tid < CITEMS - 512) tile[cur^1][r2][c2] = pf2;
        }
        __syncthreads();
    }

    float temp = expf(rt_p[0]);
    temp = fminf(fmaxf(temp, 1e-4f), 1e4f);
    float sig = sig_p[0];
    float inv2s2 = 1.f / (2.f * sig * sig);

    float m = -1e30f;
    #pragma unroll
    for (int p = 0; p < NTAP; p++) { l[p] *= temp; m = fmaxf(m, l[p]); }
    float Z = 0.f;
    #pragma unroll
    for (int p = 0; p < NTAP; p++) { l[p] = expf(l[p] - m); Z += l[p]; }
    float invZ = 1.f / Z;
    float S = 0.f;
    #pragma unroll
    for (int p = 0; p < NTAP; p++) {
        int i = p / DIAM, j = p % DIAM;
        float dy = (i - 3) * (1.f/3.f), dx = (j - 3) * (1.f/3.f);
        float sp = expf(-(dx*dx + dy*dy) * inv2s2);
        l[p] = (l[p] * invZ) * sp;
        S += l[p];
    }
    S = fmaxf(S, 1e-7f);
    float invS = 1.f / S;
    float* op = comb + (size_t)b * NTAP * plane + (size_t)y*GW + x;
    #pragma unroll
    for (int p = 0; p < NTAP; p++) op[(size_t)p * plane] = l[p] * invS;
}

// ---------------- bicubic weight helper ----------------
__device__ __forceinline__ float keysw(float x) {
    x = fabsf(x);
    if (x <= 1.f)      return ((1.5f*x - 2.5f)*x)*x + 1.f;
    else if (x < 2.f)  return ((-0.5f*x + 2.5f)*x - 4.f)*x + 2.f;
    return 0.f;
}
__device__ __forceinline__ void cubw(int o, int n, int* base, float w[4]) {
    float cc = 0.5f * o - 0.25f;
    int bb = (int)floorf(cc);
    float t = cc - (float)bb;
    w[0] = keysw(1.f + t); w[1] = keysw(t); w[2] = keysw(1.f - t); w[3] = keysw(2.f - t);
    float s = 0.f;
    #pragma unroll
    for (int k = 0; k < 4; k++) {
        int ii = bb - 1 + k;
        if (ii < 0 || ii >= n) w[k] = 0.f;
        s += w[k];
    }
    float inv = 1.f / s;
    #pragma unroll
    for (int k = 0; k < 4; k++) w[k] *= inv;
    *base = bb - 1;
}

// ---------------- FUSED bicubic 2x + adaptive 7x7 conv (R7 layout) ----------------
#define TLX 32
#define TLY 8
#define HLX 38
#define HLY 14
#define SRCW 24
#define SRCH 12
#define NHIT (HLX*SRCH)
#define NVIT (HLX*HLY)
#define NSIT (SRCW*SRCH)
#define NCHI 8
#define XPITCH 9
#define YPITCH (HLX*XPITCH)

#define OFF_S2T   0
#define OFF_TMPH  2400
#define OFF_HRT   6240
#define OFF_WSM   11028
#define OFF_WXS   23572
#define OFF_CXS   23724
#define OFF_WYS   23876
#define OFF_RYS   23932
#define DSM_FLOATS 23988

__global__ void __launch_bounds__(256, 2) jbu_fused_kernel(
        const float* __restrict__ src, const float* __restrict__ comb,
        float* __restrict__ out, int H, int W, int do_round) {
    extern __shared__ float dsm[];
    float* s2t  = dsm + OFF_S2T;
    float* tmpH = dsm + OFF_TMPH;
    float* hrt  = dsm + OFF_HRT;
    float* wsm  = dsm + OFF_WSM;
    float* wxs  = dsm + OFF_WXS;
    int*   cxs  = (int*)(dsm + OFF_CXS);
    float* wys  = dsm + OFF_WYS;
    int*   rys  = (int*)(dsm + OFF_RYS);

    int GH = 2*H, GW = 2*W;
    int tid = threadIdx.x;
    int x0 = blockIdx.x * TLX, y0 = blockIdx.y * TLY;
    int b = blockIdx.z;
    int plane = GH * GW;
    int sx0 = x0/2 - 4, sy0 = y0/2 - 4;
    int HW = H * W;

    if (tid < HLX + HLY) {
        if (tid < HLX) {
            int l = tid;
            int gx = refl(x0 - RAD + l, GW);
            int base; float w[4]; cubw(gx, W, &base, w);
            #pragma unroll
            for (int k = 0; k < 4; k++) {
                cxs[l*4+k] = min(max(base + k, 0), W-1) - sx0;
                wxs[l*4+k] = w[k];
            }
        } else {
            int l = tid - HLX;
            int gy = refl(y0 - RAD + l, GH);
            int base; float w[4]; cubw(gy, H, &base, w);
            #pragma unroll
            for (int k = 0; k < 4; k++) {
                rys[l*4+k] = min(max(base + k, 0), H-1) - sy0;
                wys[l*4+k] = w[k];
            }
        }
    }

    {
        int wr = tid >> 5, wc = tid & 31;
        const float* cp = comb + (size_t)b * NTAP * plane + (size_t)(y0+wr)*GW + (x0+wc);
        #pragma unroll 7
        for (int p = 0; p < NTAP; p++)
            wsm[p*256 + tid] = __ldg(&cp[(size_t)p * plane]);
    }

    int ch = tid & 7;
    int g  = (tid >> 3) & 3;
    int r  = tid >> 5;

    int sr0 = tid / SRCW,        sc0 = tid % SRCW;
    int sr1 = (tid+256) / SRCW,  sc1 = (tid+256) % SRCW;
    int has1 = (tid + 256 < NSIT);
    size_t o0 = (size_t)min(max(sy0 + sr0, 0), H-1)*W + min(max(sx0 + sc0, 0), W-1);
    size_t o1 = (size_t)min(max(sy0 + sr1, 0), H-1)*W + min(max(sx0 + sc1, 0), W-1);

    int h0r = tid / HLX,        h0c = tid % HLX;
    int h1r = (tid+256) / HLX,  h1c = (tid+256) % HLX;
    int hHas1 = (tid < NHIT - 256);
    int v0r = h0r,              v0c = h0c;
    int v1r = h1r,              v1c = h1c;
    int v2r = (tid+512) / HLX,  v2c = (tid+512) % HLX;
    int vHas2 = (tid < NVIT - 512);

    const float* sp = src + (size_t)b * CH * HW;
    float* opx = out + (size_t)b * CH * plane + (size_t)(y0+r)*GW + (x0 + 8*g);

    __syncthreads();

    #pragma unroll
    for (int c8 = 0; c8 < NCHI; c8++) {
        const float* cp = sp + (size_t)c8 * HW;
        s2t[c8*300 + sr0*25 + sc0] = __ldg(&cp[o0]);
        if (has1) s2t[c8*300 + sr1*25 + sc1] = __ldg(&cp[o1]);
    }
    __syncthreads();

    for (int it = 0; it < CH/NCHI; it++) {
        int c = NCHI*it;
        int havepf = (it + 1 < CH/NCHI);
        float pf0[NCHI], pf1[NCHI];
        if (havepf) {
            const float* npb = sp + (size_t)(c + NCHI) * HW;
            #pragma unroll
            for (int c8 = 0; c8 < NCHI; c8++) {
                pf0[c8] = __ldg(&npb[(size_t)c8*HW + o0]);
                if (has1) pf1[c8] = __ldg(&npb[(size_t)c8*HW + o1]);
            }
        }

        #pragma unroll
        for (int c8 = 0; c8 < NCHI; c8++) {
            float* tb = tmpH + c8*480;
            const float* sb = s2t + c8*300;
            tb[h0r*40 + h0c] = wxs[h0c*4+0]*sb[h0r*25 + cxs[h0c*4+0]]
                             + wxs[h0c*4+1]*sb[h0r*25 + cxs[h0c*4+1]]
                             + wxs[h0c*4+2]*sb[h0r*25 + cxs[h0c*4+2]]
                             + wxs[h0c*4+3]*sb[h0r*25 + cxs[h0c*4+3]];
            if (hHas1)
                tb[h1r*40 + h1c] = wxs[h1c*4+0]*sb[h1r*25 + cxs[h1c*4+0]]
                                 + wxs[h1c*4+1]*sb[h1r*25 + cxs[h1c*4+1]]
                                 + wxs[h1c*4+2]*sb[h1r*25 + cxs[h1c*4+2]]
                                 + wxs[h1c*4+3]*sb[h1r*25 + cxs[h1c*4+3]];
        }
        __syncthreads();

        if (havepf) {
            #pragma unroll
            for (int c8 = 0; c8 < NCHI; c8++) {
                s2t[c8*300 + sr0*25 + sc0] = pf0[c8];
                if (has1) s2t[c8*300 + sr1*25 + sc1] = pf1[c8];
            }
        }

        #pragma unroll
        for (int c8 = 0; c8 < NCHI; c8++) {
            const float* tb = tmpH + c8*480;
            hrt[v0r*YPITCH + v0c*XPITCH + c8]
                = wys[v0r*4+0]*tb[rys[v0r*4+0]*40 + v0c]
                + wys[v0r*4+1]*tb[rys[v0r*4+1]*40 + v0c]
                + wys[v0r*4+2]*tb[rys[v0r*4+2]*40 + v0c]
                + wys[v0r*4+3]*tb[rys[v0r*4+3]*40 + v0c];
            hrt[v1r*YPITCH + v1c*XPITCH + c8]
                = wys[v1r*4+0]*tb[rys[v1r*4+0]*40 + v1c]
                + wys[v1r*4+1]*tb[rys[v1r*4+1]*40 + v1c]
                + wys[v1r*4+2]*tb[rys[v1r*4+2]*40 + v1c]
                + wys[v1r*4+3]*tb[rys[v1r*4+3]*40 + v1c];
            if (vHas2)
                hrt[v2r*YPITCH + v2c*XPITCH + c8]
                    = wys[v2r*4+0]*tb[rys[v2r*4+0]*40 + v2c]
                    + wys[v2r*4+1]*tb[rys[v2r*4+1]*40 + v2c]
                    + wys[v2r*4+2]*tb[rys[v2r*4+2]*40 + v2c]
                    + wys[v2r*4+3]*tb[rys[v2r*4+3]*40 + v2c];
        }
        __syncthreads();

        float acc[8];
        #pragma unroll
        for (int j = 0; j < 8; j++) acc[j] = 0.f;
        #pragma unroll
        for (int i = 0; i < DIAM; i++) {
            const float* rowb = hrt + (r+i)*YPITCH + (8*g)*XPITCH + ch;
            float a[14];
            #pragma unroll
            for (int m = 0; m < 14; m++) a[m] = rowb[m*XPITCH];
            #pragma unroll
            for (int pc = 0; pc < DIAM; pc++) {
                const float4* wp4 = (const float4*)&wsm[(i*7+pc)*256 + r*32 + 8*g];
                float4 w0 = wp4[0], w1 = wp4[1];
                acc[0] += w0.x*a[pc+0]; acc[1] += w0.y*a[pc+1];
                acc[2] += w0.z*a[pc+2]; acc[3] += w0.w*a[pc+3];
                acc[4] += w1.x*a[pc+4]; acc[5] += w1.y*a[pc+5];
                acc[6] += w1.z*a[pc+6]; acc[7] += w1.w*a[pc+7];
            }
        }
        if (do_round) {
            #pragma unroll
            for (int j = 0; j < 8; j++) acc[j] = __uint_as_float(f2tf32(acc[j]));
        }
        float* dst = &opx[(size_t)(c + ch) * plane];
        *(float4*)&dst[0] = make_float4(acc[0], acc[1], acc[2], acc[3]);
        *(float4*)&dst[4] = make_float4(acc[4], acc[5], acc[6], acc[7]);
        __syncthreads();
    }
}

// ---------------- tf32 tensor-core GEMM (R7 proven config: 128x128, 256 thr) ----------------
#define GBM 128
#define GBN 128
#define GBK 16
#define GNK (CH/GBK)   // 24
#define NSTG 3

__device__ __forceinline__ void mma_tf32(float c[4],
        uint32_t a0, uint32_t a1, uint32_t a2, uint32_t a3,
        uint32_t b0, uint32_t b1) {
    asm volatile(
        "mma.sync.aligned.m16n8k8.row.col.f32.tf32.tf32.f32 "
        "{%0,%1,%2,%3},{%4,%5,%6,%7},{%8,%9},{%0,%1,%2,%3};\n"
        : "+f"(c[0]), "+f"(c[1]), "+f"(c[2]), "+f"(c[3])
        : "r"(a0), "r"(a1), "r"(a2), "r"(a3), "r"(b0), "r"(b1));
}
#define CP_ASYNC16(dst, src) \
    asm volatile("cp.async.cg.shared.global [%0], [%1], 16;\n" :: "r"(dst), "l"(src))
#define CP_COMMIT() asm volatile("cp.async.commit_group;\n" ::)
#define CP_WAIT1()  asm volatile("cp.async.wait_group 1;\n" ::)

__global__ void __launch_bounds__(256) gemm_tf32_kernel(
        const float* __restrict__ A, const float* __restrict__ Bmat,
        const float* __restrict__ bias, float* __restrict__ C, int N) {
    __shared__ float As[NSTG][GBM][20];
    __shared__ float Bs[NSTG][GBK][136];

    int tid = threadIdx.x;
    int warp = tid / 32, lane = tid % 32;
    int wm = warp / 4, wn = warp % 4;
    int g = lane / 4, tig = lane % 4;
    int bx = blockIdx.x * GBN, by = blockIdx.y * GBM;
    const float* Bb = Bmat + (size_t)blockIdx.z * CH * N;
    float* Cb = C + (size_t)blockIdx.z * OUTC * N;

    float acc[4][4][4];
    #pragma unroll
    for (int mi = 0; mi < 4; mi++)
        #pragma unroll
        for (int ni = 0; ni < 4; ni++)
            #pragma unroll
            for (int q = 0; q < 4; q++) acc[mi][ni][q] = 0.f;

    int ar0 = tid >> 2,        ac0 = (tid & 3) << 2;
    int ar1 = (tid+256) >> 2,  ac1 = ac0;
    int br0 = tid >> 5,        bc0 = (tid & 31) << 2;
    int br1 = (tid+256) >> 5,  bc1 = bc0;

    const float* a0p = &A[(size_t)(by + ar0)*CH + ac0];
    const float* a1p = &A[(size_t)(by + ar1)*CH + ac1];
    const float* b0p = &Bb[(size_t)br0*N + bx + bc0];
    const float* b1p = &Bb[(size_t)br1*N + bx + bc1];

    uint32_t sa0[NSTG], sa1[NSTG], sb0[NSTG], sb1[NSTG];
    #pragma unroll
    for (int s = 0; s < NSTG; s++) {
        sa0[s] = (uint32_t)__cvta_generic_to_shared(&As[s][ar0][ac0]);
        sa1[s] = (uint32_t)__cvta_generic_to_shared(&As[s][ar1][ac1]);
        sb0[s] = (uint32_t)__cvta_generic_to_shared(&Bs[s][br0][bc0]);
        sb1[s] = (uint32_t)__cvta_generic_to_shared(&Bs[s][br1][bc1]);
    }

    #pragma unroll
    for (int s = 0; s < 2; s++) {
        int k0 = s * GBK;
        CP_ASYNC16(sa0[s], a0p + k0);
        CP_ASYNC16(sa1[s], a1p + k0);
        CP_ASYNC16(sb0[s], b0p + (size_t)k0 * N);
        CP_ASYNC16(sb1[s], b1p + (size_t)k0 * N);
        CP_COMMIT();
    }

    for (int kt = 0; kt < GNK; kt++) {
        int cur = kt % NSTG;
        CP_WAIT1();
        __syncthreads();
        if (kt + 2 < GNK) {
            int s = (kt + 2) % NSTG;
            int k0 = (kt + 2) * GBK;
            CP_ASYNC16(sa0[s], a0p + k0);
            CP_ASYNC16(sa1[s], a1p + k0);
            CP_ASYNC16(sb0[s], b0p + (size_t)k0 * N);
            CP_ASYNC16(sb1[s], b1p + (size_t)k0 * N);
        }
        CP_COMMIT();

        #pragma unroll
        for (int ksub = 0; ksub < 2; ksub++) {
            int kb = ksub * 8;
            uint32_t af[4][4], bf[4][2];
            #pragma unroll
            for (int mi = 0; mi < 4; mi++) {
                int row = wm*64 + mi*16 + g;
                af[mi][0] = __float_as_uint(As[cur][row  ][kb + tig]);
                af[mi][1] = __float_as_uint(As[cur][row+8][kb + tig]);
                af[mi][2] = __float_as_uint(As[cur][row  ][kb + tig + 4]);
                af[mi][3] = __float_as_uint(As[cur][row+8][kb + tig + 4]);
            }
            #pragma unroll
            for (int ni = 0; ni < 4; ni++) {
                int col = wn*32 + ni*8 + g;
                bf[ni][0] = __float_as_uint(Bs[cur][kb + tig    ][col]);
                bf[ni][1] = __float_as_uint(Bs[cur][kb + tig + 4][col]);
            }
            #pragma unroll
            for (int mi = 0; mi < 4; mi++)
                #pragma unroll
                for (int ni = 0; ni < 4; ni++)
                    mma_tf32(acc[mi][ni], af[mi][0], af[mi][1], af[mi][2], af[mi][3],
                             bf[ni][0], bf[ni][1]);
        }
    }

    #pragma unroll
    for (int mi = 0; mi < 4; mi++) {
        int r0 = by + wm*64 + mi*16 + g;
        float bi0 = bias[r0], bi1 = bias[r0 + 8];
        #pragma unroll
        for (int ni = 0; ni < 4; ni++) {
            int cc = bx + wn*32 + ni*8 + tig*2;
            *(float2*)&Cb[(size_t)r0*N + cc]     = make_float2(acc[mi][ni][0]+bi0, acc[mi][ni][1]+bi0);
            *(float2*)&Cb[(size_t)(r0+8)*N + cc] = make_float2(acc[mi][ni][2]+bi1, acc[mi][ni][3]+bi1);
        }
    }
}

// ---------------- host launch: fork stage-2 prep (+weff) onto a side stream ----------------
extern "C" void kernel_launch(void* const* d_in, const int* in_sizes, int n_in,
                              void* d_out, int out_size) {
    const float* source   = (const float*)d_in[0];
    const float* guidance = (const float*)d_in[1];
    const float* u1w1 = (const float*)d_in[2];
    const float* u1b1 = (const float*)d_in[3];
    const float* u1w2 = (const float*)d_in[4];
    const float* u1b2 = (const float*)d_in[5];
    const float* u1rt = (const float*)d_in[6];
    const float* u1sg = (const float*)d_in[7];
    const float* u2w1 = (const float*)d_in[8];
    const float* u2b1 = (const float*)d_in[9];
    const float* u2w2 = (const float*)d_in[10];
    const float* u2b2 = (const float*)d_in[11];
    const float* u2rt = (const float*)d_in[12];
    const float* u2sg = (const float*)d_in[13];
    const float* fixw = (const float*)d_in[14];
    const float* fixb = (const float*)d_in[15];
    const float* prjw = (const float*)d_in[16];
    const float* prjb = (const float*)d_in[17];
    float* out = (float*)d_out;

    float *g1, *g2, *p1, *p2, *c1, *c2, *s2, *s4, *weff, *beff;
    cudaGetSymbolAddress((void**)&g1,  g_g1);
    cudaGetSymbolAddress((void**)&g2,  g_g2);
    cudaGetSymbolAddress((void**)&p1,  g_p1);
    cudaGetSymbolAddress((void**)&p2,  g_p2);
    cudaGetSymbolAddress((void**)&c1,  g_c1);
    cudaGetSymbolAddress((void**)&c2,  g_c2);
    cudaGetSymbolAddress((void**)&s2,  g_s2);
    cudaGetSymbolAddress((void**)&s4,  g_s4);
    cudaGetSymbolAddress((void**)&weff, g_weff);
    cudaGetSymbolAddress((void**)&beff, g_beff);

    const int dsm_bytes = DSM_FLOATS * 4;
    cudaFuncSetAttribute(jbu_fused_kernel,
                         cudaFuncAttributeMaxDynamicSharedMemorySize, dsm_bytes);

    // side stream + fork/join events, created once on the first (uncaptured) call
    static cudaStream_t sB = (cudaStream_t)0;
    static cudaEvent_t evFork = (cudaEvent_t)0, evJoin = (cudaEvent_t)0;
    static int sInit = 0;
    if (!sInit) {
        sInit = 1;
        if (cudaStreamCreateWithFlags(&sB, cudaStreamNonBlocking) != cudaSuccess) sB = (cudaStream_t)0;
        if (cudaEventCreateWithFlags(&evFork, cudaEventDisableTiming) != cudaSuccess) evFork = (cudaEvent_t)0;
        if (cudaEventCreateWithFlags(&evJoin, cudaEventDisableTiming) != cudaSuccess) evJoin = (cudaEvent_t)0;
    }
    bool fork = (sB != (cudaStream_t)0) && (evFork != (cudaEvent_t)0) && (evJoin != (cudaEvent_t)0);
    cudaStream_t s2strm = fork ? sB : (cudaStream_t)0;

    if (fork) {
        cudaEventRecord(evFork, (cudaStream_t)0);
        cudaStreamWaitEvent(sB, evFork, 0);
    }

    // ---- branch B (side stream): stage-2 prep + weff ----
    pool_kernel<<<(BATCH*3*192*192 + 255)/256, 256, 0, s2strm>>>(guidance, g2, 192, 192, 4);
    rproj_kernel<<<(BATCH*192*192 + 255)/256, 256, 0, s2strm>>>(g2, u2w1, u2b1, u2w2, u2b2, p2, 192, 192);
    comb_tiled_kernel<<<dim3(192/CTX, 192/CTY, BATCH), 256, 0, s2strm>>>(p2, u2rt, u2sg, c2, 192, 192);
    weff_kernel<<<dim3(CH/WTN, OUTC/WTM), 256, 0, s2strm>>>(prjw, prjb, fixw, fixb, weff, beff);
    if (fork) cudaEventRecord(evJoin, sB);

    // ---- branch A (main stream): stage-1 chain ----
    pool_kernel<<<(BATCH*3*96*96 + 255)/256, 256>>>(guidance, g1, 96, 96, 8);
    rproj_kernel<<<(BATCH*96*96 + 255)/256, 256>>>(g1, u1w1, u1b1, u1w2, u1b2, p1, 96, 96);
    comb_tiled_kernel<<<dim3(96/CTX, 96/CTY, BATCH), 256>>>(p1, u1rt, u1sg, c1, 96, 96);
    jbu_fused_kernel<<<dim3(96/TLX, 96/TLY, BATCH), 256, dsm_bytes>>>(source, c1, s2, 48, 48, 0);

    // ---- join, then stage-2 jbu + GEMM on main stream ----
    if (fork) cudaStreamWaitEvent((cudaStream_t)0, evJoin, 0);
    jbu_fused_kernel<<<dim3(192/TLX, 192/TLY, BATCH), 256, dsm_bytes>>>(s2, c2, s4, 96, 96, 1);
    gemm_tf32_kernel<<<dim3(192*192/GBN, OUTC/GBM, BATCH), 256>>>(weff, s4, beff, out, 192*192);
}